// round 2
// baseline (speedup 1.0000x reference)
#include <cuda_runtime.h>
#include <cstdint>

// Problem constants
#define B_N   8
#define C_IN  64
#define C_OUT 64
#define HW    256
#define KS    31
#define PADP  15

// Tiling
#define TY 16
#define TX 16
#define CCH 8                                // input-channel chunk per K step
#define PATCH_W (TX + KS - 1)                // 46
#define PATCH_XS CCH                         // 8 words per x position
#define PATCH_YS (PATCH_W * PATCH_XS + 8)    // 376 words (padded)
#define PATCH_WORDS (TY * PATCH_YS)          // 6016
#define WSM_WORDS (KS * C_OUT * CCH)         // 15872
#define SMEM_BYTES ((PATCH_WORDS + WSM_WORDS) * 4)

#define NTHREADS 256

// Scratch: weights transposed to [u][v][c][o], tf32-rounded (15.7 MB)
__device__ float g_wT[KS * KS * C_IN * C_OUT];

__global__ void wtrans_kernel(const float* __restrict__ w) {
    int i = blockIdx.x * blockDim.x + threadIdx.x;
    const int total = C_OUT * C_IN * KS * KS;
    if (i >= total) return;
    int v = i % KS;
    int t = i / KS;
    int u = t % KS;  t /= KS;
    int c = t % C_IN;
    int o = t / C_IN;
    float val = w[i];
    uint32_t tv;
    asm("cvt.rna.tf32.f32 %0, %1;" : "=r"(tv) : "f"(val));
    g_wT[((u * KS + v) * C_IN + c) * C_OUT + o] = __uint_as_float(tv);
}

// Direct conv as shift-GEMM with mma.sync m16n8k8 tf32.
// CTA: one (b, 16y x 16x) output tile, all 64 output channels.
// Warp w handles output rows y_loc = {2w, 2w+1} (two m16 frags), all 64 o (8 n8 frags).
__global__ void __launch_bounds__(NTHREADS, 2)
conv_kernel(const float* __restrict__ sig,
            const float* __restrict__ bias,
            float* __restrict__ out)
{
    extern __shared__ float sm[];
    float* patch = sm;                  // [yt][xi][sigma(c)]  (TY x 46 x 8, padded)
    float* wsm   = sm + PATCH_WORDS;    // [v][o][tig] float2 pairs (b0,b1)

    const int x0 = blockIdx.x * TX;
    const int y0 = blockIdx.y * TY;
    const int b  = blockIdx.z;

    const int tid  = threadIdx.x;
    const int wrp  = tid >> 5;
    const int lane = tid & 31;
    const int gid  = lane >> 2;   // 0..7
    const int tig  = lane & 3;    // 0..3

    float acc[2][8][4];
    #pragma unroll
    for (int mi = 0; mi < 2; mi++)
      #pragma unroll
      for (int nf = 0; nf < 8; nf++)
        #pragma unroll
        for (int r = 0; r < 4; r++)
          acc[mi][nf][r] = 0.f;

    for (int c0 = 0; c0 < C_IN; c0 += CCH) {
      for (int u = 0; u < KS; u++) {
        __syncthreads();
        // ---- stage input patch: rows y0+yt+u-15, cols x0-15..x0+30, channels c0..c0+7 ----
        for (int i = tid; i < TY * PATCH_W * CCH; i += NTHREADS) {
          int yt = i / (PATCH_W * CCH);
          int r  = i - yt * (PATCH_W * CCH);
          int c  = r / PATCH_W;
          int xi = r - c * PATCH_W;
          int row = y0 + yt + u - PADP;
          int col = x0 + xi - PADP;
          float vs = 0.f;
          if ((unsigned)row < HW && (unsigned)col < HW)
            vs = sig[((b * C_IN + c0 + c) * HW + row) * HW + col];
          uint32_t tv;
          asm("cvt.rna.tf32.f32 %0, %1;" : "=r"(tv) : "f"(vs));
          // interleave c so (c=tig, c=tig+4) are adjacent -> one LDS.64 per A reg pair
          int sc = ((c & 3) << 1) | (c >> 2);
          patch[yt * PATCH_YS + xi * PATCH_XS + sc] = __uint_as_float(tv);
        }
        // ---- stage weights for (u, c-chunk): [v][o] float2 {B[c=tig][o], B[c=tig+4][o]} ----
        {
          const float* wsrc = g_wT + u * (KS * C_IN * C_OUT) + c0 * C_OUT;
          for (int i = tid; i < KS * CCH * C_OUT; i += NTHREADS) {
            int o = i & (C_OUT - 1);
            int c = (i >> 6) & (CCH - 1);
            int v = i >> 9;
            float val = wsrc[v * (C_IN * C_OUT) + c * C_OUT + o];
            int widx = (((v * C_OUT + o) << 2) | (c & 3)) * 2 + (c >> 2);
            wsm[widx] = val;
          }
        }
        __syncthreads();

        // ---- compute: 31 v-shifts, each a M256xN64xK8 GEMM step ----
        const float* pbase0 = patch + (2 * wrp) * PATCH_YS + gid * PATCH_XS + tig * 2;
        const float* pbase1 = pbase0 + PATCH_YS;
        for (int v = 0; v < KS; v++) {
          float2 bf[8];
          const float* wb = wsm + v * (C_OUT * 8) + gid * 8 + tig * 2;
          #pragma unroll
          for (int nf = 0; nf < 8; nf++)
            bf[nf] = *(const float2*)(wb + nf * 64);
          #pragma unroll
          for (int mi = 0; mi < 2; mi++) {
            const float* ap = (mi ? pbase1 : pbase0) + v * PATCH_XS;
            float2 a02 = *(const float2*)(ap);                 // {a0, a2} at x = gid+v
            float2 a13 = *(const float2*)(ap + 8 * PATCH_XS);  // {a1, a3} at x = gid+8+v
            #pragma unroll
            for (int nf = 0; nf < 8; nf++) {
              asm volatile(
                "mma.sync.aligned.m16n8k8.row.col.f32.tf32.tf32.f32 "
                "{%0,%1,%2,%3}, {%4,%5,%6,%7}, {%8,%9}, {%0,%1,%2,%3};"
                : "+f"(acc[mi][nf][0]), "+f"(acc[mi][nf][1]),
                  "+f"(acc[mi][nf][2]), "+f"(acc[mi][nf][3])
                : "r"(__float_as_uint(a02.x)), "r"(__float_as_uint(a13.x)),
                  "r"(__float_as_uint(a02.y)), "r"(__float_as_uint(a13.y)),
                  "r"(__float_as_uint(bf[nf].x)), "r"(__float_as_uint(bf[nf].y)));
            }
          }
        }
      }
    }

    // ---- epilogue: C frag -> out[b][o][y][x] + bias[o] ----
    #pragma unroll
    for (int mi = 0; mi < 2; mi++) {
      int y = y0 + 2 * wrp + mi;
      #pragma unroll
      for (int nf = 0; nf < 8; nf++) {
        int on = nf * 8 + tig * 2;
        float bv0 = __ldg(&bias[on]);
        float bv1 = __ldg(&bias[on + 1]);
        int xa = x0 + gid;
        int xb = xa + 8;
        int base0 = ((b * C_OUT + on) * HW + y) * HW;
        int base1 = ((b * C_OUT + on + 1) * HW + y) * HW;
        out[base0 + xa] = acc[mi][nf][0] + bv0;   // row gid,   col tig*2
        out[base1 + xa] = acc[mi][nf][1] + bv1;   // row gid,   col tig*2+1
        out[base0 + xb] = acc[mi][nf][2] + bv0;   // row gid+8, col tig*2
        out[base1 + xb] = acc[mi][nf][3] + bv1;   // row gid+8, col tig*2+1
      }
    }
}

extern "C" void kernel_launch(void* const* d_in, const int* in_sizes, int n_in,
                              void* d_out, int out_size) {
    const float* sig  = (const float*)d_in[0];
    const float* wgt  = (const float*)d_in[1];
    const float* bias = (const float*)d_in[2];
    float* out = (float*)d_out;

    cudaFuncSetAttribute(conv_kernel, cudaFuncAttributeMaxDynamicSharedMemorySize,
                         SMEM_BYTES);

    const int wtotal = C_OUT * C_IN * KS * KS;
    wtrans_kernel<<<(wtotal + 255) / 256, 256>>>(wgt);

    dim3 grid(HW / TX, HW / TY, B_N);
    conv_kernel<<<grid, NTHREADS, SMEM_BYTES>>>(sig, bias, out);
}

// round 6
// speedup vs baseline: 1.6224x; 1.6224x over previous
#include <cuda_runtime.h>
#include <cstdint>
#include <cstddef>

#define B_N   8
#define C_IN  64
#define C_OUT 64
#define HW    256
#define KS    31
#define NCC   8                 // 8 channel-chunks of 8
#define NITER (NCC*KS)          // 248

#define TXT   16                // x per CTA (one m16 across gid/gid+8)
#define TYT   32                // y rows per CTA (8 warps x 4 rows)
#define YPADN 286               // padded rows: piy = y + 15, y in [-15,270]
#define XPADN 292               // padded cols: px = x + 16
#define RSL   33                // ring slots
#define ROWF  52                // floats4-pairs... 52 x-positions staged per row
#define ROWB  (ROWF*32)         // 1664 bytes per row (52 px * 8 words)
#define WBLKB (KS*C_OUT*8*4)    // 63488 bytes per (cc,u) weight block
#define SM_W_OFF (RSL*ROWB)     // 54912
#define SMEM_TOTAL (SM_W_OFF + 2*WBLKB)   // 181888

// ---------------- device scratch ----------------
// padded, tf32-rounded, channel-interleaved input: [b][cc][piy][px][2xfloat4]
__device__ float4 g_sP4[(size_t)B_N * NCC * YPADN * XPADN * 2];   // ~171 MB
// weights: per iteration block i=cc*31+u: [v][o][2xfloat4], interleaved like A
__device__ float4 g_w24[(size_t)NITER * KS * C_OUT * 2];          // ~15.9 MB

__device__ __forceinline__ float tf32r(float x) {
    uint32_t t; asm("cvt.rna.tf32.f32 %0, %1;" : "=r"(t) : "f"(x));
    return __uint_as_float(t);
}
__device__ __forceinline__ uint32_t smem_u32(const void* p) {
    uint32_t a;
    asm("{ .reg .u64 t; cvta.to.shared.u64 t, %1; cvt.u32.u64 %0, t; }" : "=r"(a) : "l"(p));
    return a;
}
__device__ __forceinline__ void cpa16(uint32_t dst, const void* src) {
    asm volatile("cp.async.cg.shared.global [%0], [%1], 16;" :: "r"(dst), "l"(src));
}
__device__ __forceinline__ void cpa_commit() {
    asm volatile("cp.async.commit_group;");
}
__device__ __forceinline__ void cpa_wait0() {
    asm volatile("cp.async.wait_group 0;");
}
__device__ __forceinline__ void hmma(float* acc, float2 a02, float2 a13, float2 b01) {
    asm volatile(
        "mma.sync.aligned.m16n8k8.row.col.f32.tf32.tf32.f32 "
        "{%0,%1,%2,%3}, {%4,%5,%6,%7}, {%8,%9}, {%0,%1,%2,%3};"
        : "+f"(acc[0]), "+f"(acc[1]), "+f"(acc[2]), "+f"(acc[3])
        : "r"(__float_as_uint(a02.x)), "r"(__float_as_uint(a13.x)),
          "r"(__float_as_uint(a02.y)), "r"(__float_as_uint(a13.y)),
          "r"(__float_as_uint(b01.x)), "r"(__float_as_uint(b01.y)));
}

// ---------------- pre-pass: pad + round + interleave signal ----------------
// thread per (b, cc, piy, px): gathers 8 channels, writes 2 float4 (32B, coalesced)
__global__ void prep_sig(const float* __restrict__ sig) {
    size_t idx = (size_t)blockIdx.x * 256 + threadIdx.x;
    const size_t total = (size_t)B_N * NCC * YPADN * XPADN;
    if (idx >= total) return;
    int px  = (int)(idx % XPADN); size_t t = idx / XPADN;
    int piy = (int)(t % YPADN);   t /= YPADN;
    int cc  = (int)(t & 7);       int b = (int)(t >> 3);
    int y = piy - 15, x = px - 16;
    float wv[8];
    #pragma unroll
    for (int k = 0; k < 8; k++) wv[k] = 0.f;
    if ((unsigned)y < HW && (unsigned)x < HW) {
        const float* s = sig + (((size_t)(b * C_IN + cc * 8) * HW + y) * HW + x);
        #pragma unroll
        for (int k = 0; k < 8; k++) {
            int sc = ((k & 3) << 1) | (k >> 2);
            wv[sc] = tf32r(s[(size_t)k * HW * HW]);
        }
    }
    float4* dst = g_sP4 + idx * 2;
    dst[0] = make_float4(wv[0], wv[1], wv[2], wv[3]);
    dst[1] = make_float4(wv[4], wv[5], wv[6], wv[7]);
}

// ---------------- pre-pass: transpose + round + interleave weights ----------
// thread per (block=cc*31+u, v, o): 8 channel values -> 2 float4
__global__ void prep_w(const float* __restrict__ w) {
    size_t idx = (size_t)blockIdx.x * 256 + threadIdx.x;
    const size_t total = (size_t)NITER * KS * C_OUT;
    if (idx >= total) return;
    int o = (int)(idx & 63); size_t t = idx >> 6;
    int v = (int)(t % KS);   t /= KS;
    int u = (int)(t % KS);   int cc = (int)(t / KS);
    float wv[8];
    #pragma unroll
    for (int k = 0; k < 8; k++) {
        int sc = ((k & 3) << 1) | (k >> 2);
        wv[sc] = tf32r(w[(((size_t)o * C_IN + cc * 8 + k) * KS + u) * KS + v]);
    }
    float4* dst = g_w24 + idx * 2;
    dst[0] = make_float4(wv[0], wv[1], wv[2], wv[3]);
    dst[1] = make_float4(wv[4], wv[5], wv[6], wv[7]);
}

// ---------------- main conv kernel ----------------
__global__ void __launch_bounds__(256, 1)
conv_kernel(const float* __restrict__ bias, float* __restrict__ out)
{
    extern __shared__ __align__(128) char smem[];
    const uint32_t sb = smem_u32(smem);
    const int x0 = blockIdx.x * TXT;
    const int y0 = blockIdx.y * TYT;
    const int b  = blockIdx.z;
    const int tid  = threadIdx.x;
    const int wrp  = tid >> 5;
    const int lane = tid & 31;
    const int gid  = lane >> 2;
    const int tig  = lane & 3;

    // ---- staging helpers (all threads cooperate) ----
    auto stage_weights = [&](int it) {
        const float4* src = g_w24 + (size_t)it * (KS * C_OUT * 2);
        uint32_t dst = sb + SM_W_OFF + (uint32_t)(it & 1) * WBLKB;
        #pragma unroll 4
        for (int t = tid; t < KS * C_OUT * 2; t += 256)   // 3968 float4
            cpa16(dst + (uint32_t)t * 16, src + t);
    };
    auto stage_row = [&](int cc, int r) {                 // one padded input row
        int slot = r % RSL;
        const float4* src = g_sP4 +
            ((((size_t)(b * NCC + cc) * YPADN + (size_t)(y0 + r)) * XPADN) + x0) * 2;
        uint32_t dst = sb + (uint32_t)slot * ROWB;
        if (tid < 104)                                    // 104 float4 = 1664B
            cpa16(dst + (uint32_t)tid * 16, src + tid);
    };
    auto stage32 = [&](int cc) {                          // rows r=0..31 (c0 boundary)
        for (int t = tid; t < 32 * 104; t += 256) {
            int r = t / 104, c = t - r * 104;
            const float4* src = g_sP4 +
                ((((size_t)(b * NCC + cc) * YPADN + (size_t)(y0 + r)) * XPADN) + x0) * 2 + c;
            cpa16(sb + (uint32_t)r * ROWB + (uint32_t)c * 16, src);
        }
    };

    // ---- prologue: rows 0..31 of cc=0 and weights for iter 0 ----
    stage32(0);
    stage_weights(0);
    cpa_commit();

    float acc[4][8][4];
    #pragma unroll
    for (int mi = 0; mi < 4; mi++)
      #pragma unroll
      for (int nf = 0; nf < 8; nf++)
        #pragma unroll
        for (int r = 0; r < 4; r++)
          acc[mi][nf][r] = 0.f;

    cpa_wait0();
    __syncthreads();

    int cc = 0, u = 0;
    for (int i = 0; i < NITER; i++) {
        // ---- prefetch next iteration (overlapped with compute) ----
        bool last = (i == NITER - 1);
        bool bnd  = (u == KS - 1);          // next iter starts a new channel chunk
        if (!last) {
            if (!bnd) stage_row(cc, u + 32);   // slot (u+32)%33, disjoint from readers
            stage_weights(i + 1);              // alternate buffer, disjoint
            cpa_commit();
        }

        // ---- compute this iteration ----
        {
            const float* wsm = (const float*)(smem + SM_W_OFF + (i & 1) * WBLKB);
            const float* rowp[4];
            #pragma unroll
            for (int mi = 0; mi < 4; mi++) {
                int s = wrp * 4 + mi + u;
                if (s >= RSL) s -= RSL;
                rowp[mi] = (const float*)(smem + s * ROWB) + tig * 2;
            }
            const float* wb0 = wsm + gid * 8 + tig * 2;
            #pragma unroll 1
            for (int v = 0; v < KS; v++) {
                float2 bf[8];
                const float* wb = wb0 + v * 512;
                #pragma unroll
                for (int nf = 0; nf < 8; nf++)
                    bf[nf] = *(const float2*)(wb + nf * 64);
                #pragma unroll
                for (int mi = 0; mi < 4; mi++) {
                    const float* ap = rowp[mi] + (gid + v + 1) * 8;
                    float2 a02 = *(const float2*)(ap);
                    float2 a13 = *(const float2*)(ap + 64);   // x + 8
                    #pragma unroll
                    for (int nf = 0; nf < 8; nf++)
                        hmma(acc[mi][nf], a02, a13, bf[nf]);
                }
            }
        }

        // ---- retire prefetch / handle chunk boundary ----
        if (!last) {
            if (!bnd) {
                cpa_wait0();
                __syncthreads();
                u++;
            } else {
                __syncthreads();               // all warps done reading the ring
                stage32(cc + 1);               // reload rows 0..31 for next chunk
                cpa_commit();
                cpa_wait0();                   // weights(i+1) + rows complete
                __syncthreads();
                cc++; u = 0;
            }
        }
    }

    // ---- epilogue ----
    #pragma unroll
    for (int mi = 0; mi < 4; mi++) {
        int y = y0 + wrp * 4 + mi;
        #pragma unroll
        for (int nf = 0; nf < 8; nf++) {
            int on = nf * 8 + tig * 2;
            float bv0 = __ldg(&bias[on]);
            float bv1 = __ldg(&bias[on + 1]);
            int xa = x0 + gid;
            int xb = xa + 8;
            size_t base0 = ((size_t)(b * C_OUT + on) * HW + y) * HW;
            size_t base1 = ((size_t)(b * C_OUT + on + 1) * HW + y) * HW;
            out[base0 + xa] = acc[mi][nf][0] + bv0;
            out[base1 + xa] = acc[mi][nf][1] + bv1;
            out[base0 + xb] = acc[mi][nf][2] + bv0;
            out[base1 + xb] = acc[mi][nf][3] + bv1;
        }
    }
}

// ---------------- launch ----------------
extern "C" void kernel_launch(void* const* d_in, const int* in_sizes, int n_in,
                              void* d_out, int out_size) {
    const float* sig  = (const float*)d_in[0];
    const float* wgt  = (const float*)d_in[1];
    const float* bias = (const float*)d_in[2];
    float* out = (float*)d_out;

    static bool attr_set = false;
    if (!attr_set) {
        cudaFuncSetAttribute(conv_kernel, cudaFuncAttributeMaxDynamicSharedMemorySize,
                             SMEM_TOTAL);
        attr_set = true;
    }

    {
        const size_t total = (size_t)B_N * NCC * YPADN * XPADN;
        prep_sig<<<(unsigned)((total + 255) / 256), 256>>>(sig);
    }
    {
        const size_t total = (size_t)NITER * KS * C_OUT;
        prep_w<<<(unsigned)((total + 255) / 256), 256>>>(wgt);
    }
    dim3 grid(HW / TXT, HW / TYT, B_N);
    conv_kernel<<<grid, 256, SMEM_TOTAL>>>(bias, out);
}

// round 8
// speedup vs baseline: 3.0109x; 1.8559x over previous
#include <cuda_runtime.h>
#include <cuda_fp16.h>
#include <cstdint>
#include <cstddef>

#define B_N   8
#define C_IN  64
#define C_OUT 64
#define HW    256
#define KS    31
#define NCH   16                // channels per chunk (K=16 per mma)
#define NCC   4                 // 4 channel chunks
#define NITER (NCC*KS)          // 124

#define TXT   16
#define TYT   32
#define YPADN 286
#define XPADN 292
#define RSL   33                // ring slots
#define ROWU  94                // uint4 per staged row (47 x-positions * 32B)
#define ROWB  (ROWU*16)         // 1504 bytes
#define WBLKB (KS*C_OUT*32)     // 63488 bytes per (cc,u) weight block
#define SM_W_OFF (RSL*ROWB)     // 49632
#define SMEM_TOTAL (SM_W_OFF + 2*WBLKB)   // 176608

// ---------------- device scratch ----------------
// padded fp16 signal, 16 ch interleaved per x as units {c2t,c2t+1,c2t+8,c2t+9}:
// [b][cc][piy][px] -> 2 uint4 (32B)
__device__ uint4 g_sH[(size_t)B_N * NCC * YPADN * XPADN * 2];     // ~85.5 MB
// fp16 weights per iter block i=cc*31+u: [v][o] -> 2 uint4 (32B), same interleave
__device__ uint4 g_wH[(size_t)NITER * KS * C_OUT * 2];            // ~7.9 MB

__device__ __forceinline__ uint32_t smem_u32(const void* p) {
    uint32_t a;
    asm("{ .reg .u64 t; cvta.to.shared.u64 t, %1; cvt.u32.u64 %0, t; }" : "=r"(a) : "l"(p));
    return a;
}
__device__ __forceinline__ void cpa16(uint32_t dst, const void* src) {
    asm volatile("cp.async.cg.shared.global [%0], [%1], 16;" :: "r"(dst), "l"(src));
}
__device__ __forceinline__ void cpa_commit() { asm volatile("cp.async.commit_group;"); }
__device__ __forceinline__ void cpa_wait0()  { asm volatile("cp.async.wait_group 0;"); }

__device__ __forceinline__ void hmma16(float* acc, uint32_t a0, uint32_t a1,
                                       uint32_t a2, uint32_t a3,
                                       uint32_t b0, uint32_t b1) {
    asm volatile(
        "mma.sync.aligned.m16n8k16.row.col.f32.f16.f16.f32 "
        "{%0,%1,%2,%3}, {%4,%5,%6,%7}, {%8,%9}, {%0,%1,%2,%3};"
        : "+f"(acc[0]), "+f"(acc[1]), "+f"(acc[2]), "+f"(acc[3])
        : "r"(a0), "r"(a1), "r"(a2), "r"(a3), "r"(b0), "r"(b1));
}

// ---------------- pre-pass: pad + fp16 + interleave signal ----------------
// thread per (b, cc, piy, px): gather 16 channels, write 32B
__global__ void prep_sig(const float* __restrict__ sig) {
    size_t idx = (size_t)blockIdx.x * 256 + threadIdx.x;
    const size_t total = (size_t)B_N * NCC * YPADN * XPADN;
    if (idx >= total) return;
    int px  = (int)(idx % XPADN); size_t t = idx / XPADN;
    int piy = (int)(t % YPADN);   t /= YPADN;
    int cc  = (int)(t & 3);       int b = (int)(t >> 2);
    int y = piy - 15, x = px - 16;
    __half h[16];
    #pragma unroll
    for (int k = 0; k < 16; k++) h[k] = __float2half_rn(0.f);
    if ((unsigned)y < HW && (unsigned)x < HW) {
        const float* s = sig + (((size_t)(b * C_IN + cc * NCH) * HW + y) * HW + x);
        #pragma unroll
        for (int k = 0; k < 16; k++)
            h[k] = __float2half_rn(s[(size_t)k * HW * HW]);
    }
    __half o16[16];
    #pragma unroll
    for (int u = 0; u < 4; u++) {
        o16[u*4+0] = h[2*u];  o16[u*4+1] = h[2*u+1];
        o16[u*4+2] = h[2*u+8]; o16[u*4+3] = h[2*u+9];
    }
    const uint4* src = (const uint4*)o16;
    g_sH[idx*2]   = src[0];
    g_sH[idx*2+1] = src[1];
}

// ---------------- pre-pass: transpose + fp16 + interleave weights ----------
__global__ void prep_w(const float* __restrict__ w) {
    size_t idx = (size_t)blockIdx.x * 256 + threadIdx.x;
    const size_t total = (size_t)NITER * KS * C_OUT;
    if (idx >= total) return;
    int o = (int)(idx & 63); size_t t = idx >> 6;
    int v = (int)(t % KS);
    int i = (int)(t / KS);          // block = cc*31+u
    int u = i % KS, cc = i / KS;
    __half h[16];
    #pragma unroll
    for (int k = 0; k < 16; k++)
        h[k] = __float2half_rn(w[(((size_t)o * C_IN + cc * NCH + k) * KS + u) * KS + v]);
    __half o16[16];
    #pragma unroll
    for (int q = 0; q < 4; q++) {
        o16[q*4+0] = h[2*q];   o16[q*4+1] = h[2*q+1];
        o16[q*4+2] = h[2*q+8]; o16[q*4+3] = h[2*q+9];
    }
    const uint4* src = (const uint4*)o16;
    g_wH[idx*2]   = src[0];
    g_wH[idx*2+1] = src[1];
}

// ---------------- main conv kernel ----------------
__global__ void __launch_bounds__(256, 1)
conv_kernel(const float* __restrict__ bias, float* __restrict__ out)
{
    extern __shared__ __align__(128) char smem[];
    const uint32_t sb = smem_u32(smem);
    const int x0 = blockIdx.x * TXT;
    const int y0 = blockIdx.y * TYT;
    const int b  = blockIdx.z;
    const int tid  = threadIdx.x;
    const int wrp  = tid >> 5;
    const int lane = tid & 31;
    const int gid  = lane >> 2;
    const int tig  = lane & 3;

    auto stage_weights = [&](int it) {
        const uint4* src = g_wH + (size_t)it * (KS * C_OUT * 2);
        uint32_t dst = sb + SM_W_OFF + (uint32_t)(it & 1) * WBLKB;
        #pragma unroll 4
        for (int t = tid; t < KS * C_OUT * 2; t += 256)   // 3968 uint4
            cpa16(dst + (uint32_t)t * 16, src + t);
    };
    auto stage_row = [&](int cc, int r) {
        int slot = r % RSL;
        const uint4* src = g_sH +
            ((((size_t)(b * NCC + cc) * YPADN + (size_t)(y0 + r)) * XPADN) + x0) * 2;
        uint32_t dst = sb + (uint32_t)slot * ROWB;
        if (tid < ROWU)
            cpa16(dst + (uint32_t)tid * 16, src + tid);
    };
    auto stage32 = [&](int cc) {
        for (int t = tid; t < 32 * ROWU; t += 256) {
            int r = t / ROWU, c = t - r * ROWU;
            const uint4* src = g_sH +
                ((((size_t)(b * NCC + cc) * YPADN + (size_t)(y0 + r)) * XPADN) + x0) * 2 + c;
            cpa16(sb + (uint32_t)(r % RSL) * ROWB + (uint32_t)c * 16, src);
        }
    };

    stage32(0);
    stage_weights(0);
    cpa_commit();

    float acc[4][8][4];
    #pragma unroll
    for (int mi = 0; mi < 4; mi++)
      #pragma unroll
      for (int nf = 0; nf < 8; nf++)
        #pragma unroll
        for (int r = 0; r < 4; r++)
          acc[mi][nf][r] = 0.f;

    cpa_wait0();
    __syncthreads();

    int cc = 0, u = 0;
    for (int i = 0; i < NITER; i++) {
        bool last = (i == NITER - 1);
        bool bnd  = (u == KS - 1);
        if (!last) {
            if (!bnd) stage_row(cc, u + 32);
            stage_weights(i + 1);
            cpa_commit();
        }

        // ---- compute ----
        {
            const char* rowp[4];
            #pragma unroll
            for (int mi = 0; mi < 4; mi++) {
                int s = wrp * 4 + mi + u;
                if (s >= RSL) s -= RSL;
                rowp[mi] = smem + s * ROWB + tig * 8;
            }
            const char* wb0 = smem + SM_W_OFF + (i & 1) * WBLKB + gid * 32 + tig * 8;
            #pragma unroll 1
            for (int v = 0; v < KS; v++) {
                uint2 bf[8];
                const char* wb = wb0 + v * 2048;
                #pragma unroll
                for (int nf = 0; nf < 8; nf++)
                    bf[nf] = *(const uint2*)(wb + nf * 256);
                #pragma unroll
                for (int mi = 0; mi < 4; mi++) {
                    const char* ap = rowp[mi] + (gid + v + 1) * 32;
                    uint2 alo = *(const uint2*)(ap);          // (a0, a2) at x
                    uint2 ahi = *(const uint2*)(ap + 256);    // (a1, a3) at x+8
                    #pragma unroll
                    for (int nf = 0; nf < 8; nf++)
                        hmma16(acc[mi][nf], alo.x, ahi.x, alo.y, ahi.y,
                               bf[nf].x, bf[nf].y);
                }
            }
        }

        if (!last) {
            if (!bnd) {
                cpa_wait0();
                __syncthreads();
                u++;
            } else {
                __syncthreads();
                stage32(cc + 1);
                cpa_commit();
                cpa_wait0();
                __syncthreads();
                cc++; u = 0;
            }
        }
    }

    // ---- epilogue ----
    #pragma unroll
    for (int mi = 0; mi < 4; mi++) {
        int y = y0 + wrp * 4 + mi;
        #pragma unroll
        for (int nf = 0; nf < 8; nf++) {
            int on = nf * 8 + tig * 2;
            float bv0 = __ldg(&bias[on]);
            float bv1 = __ldg(&bias[on + 1]);
            int xa = x0 + gid;
            int xb = xa + 8;
            size_t base0 = ((size_t)(b * C_OUT + on) * HW + y) * HW;
            size_t base1 = ((size_t)(b * C_OUT + on + 1) * HW + y) * HW;
            out[base0 + xa] = acc[mi][nf][0] + bv0;
            out[base1 + xa] = acc[mi][nf][1] + bv1;
            out[base0 + xb] = acc[mi][nf][2] + bv0;
            out[base1 + xb] = acc[mi][nf][3] + bv1;
        }
    }
}

// ---------------- launch ----------------
extern "C" void kernel_launch(void* const* d_in, const int* in_sizes, int n_in,
                              void* d_out, int out_size) {
    const float* sig  = (const float*)d_in[0];
    const float* wgt  = (const float*)d_in[1];
    const float* bias = (const float*)d_in[2];
    float* out = (float*)d_out;

    static bool attr_set = false;
    if (!attr_set) {
        cudaFuncSetAttribute(conv_kernel, cudaFuncAttributeMaxDynamicSharedMemorySize,
                             SMEM_TOTAL);
        attr_set = true;
    }

    {
        const size_t total = (size_t)B_N * NCC * YPADN * XPADN;
        prep_sig<<<(unsigned)((total + 255) / 256), 256>>>(sig);
    }
    {
        const size_t total = (size_t)NITER * KS * C_OUT;
        prep_w<<<(unsigned)((total + 255) / 256), 256>>>(wgt);
    }
    dim3 grid(HW / TXT, HW / TYT, B_N);
    conv_kernel<<<grid, 256, SMEM_TOTAL>>>(bias, out);
}